// round 6
// baseline (speedup 1.0000x reference)
#include <cuda_runtime.h>
#include <cstdint>
#include <cstddef>

// Problem dims
#define BDIM 4096
#define KDIM 1024
#define HDIM 1024
#define NDIM 6144           // 6 gates * H

// GEMM tiling: CTA 128x128, 8 warps of 64x32, 2 CTAs/SM, 2-stage cp.async
#define BM 128
#define BN 128
#define BK 32
#define SS 48               // smem row stride in floats (192B): LDS.128 conflict-free
#define SQ 12               // row stride in float4
#define TILE_FLOATS (128 * SS)   // 6144 floats = 24 KB
#define NK 64                    // 2 x (1024/32)

// Scratch: Z[B,6H] (gate-4 slot holds wx4), U4[B,H] holds uh4
__device__ float g_Z[(size_t)BDIM * NDIM];
__device__ float g_U4[(size_t)BDIM * HDIM];

__device__ __forceinline__ void cp_async16(void* smem_ptr, const void* gmem_ptr) {
    uint32_t s = (uint32_t)__cvta_generic_to_shared(smem_ptr);
    asm volatile("cp.async.cg.shared.global [%0], [%1], 16;\n" :: "r"(s), "l"(gmem_ptr));
}

// One fused GEMM: Z = x*W^T + h*U^T (joint K=2048) for all gates; gate-4 tiles
// flush wx4 at the K midpoint and restart accumulation for uh4 -> U4.
__global__ __launch_bounds__(256, 2)
void xlstm_gemm_kernel(const float* __restrict__ xin, const float* __restrict__ hin,
                       const float* __restrict__ W,   const float* __restrict__ U,
                       float* __restrict__ Z, float* __restrict__ U4) {
    extern __shared__ float smem[];
    // layout: As[2][TILE_FLOATS], Bs[2][TILE_FLOATS]

    const int tid  = threadIdx.x;
    const int warp = tid >> 5;
    const int lane = tid & 31;
    const int wm = warp & 1;        // 2 warps along M (64 rows each)
    const int wn = warp >> 1;       // 4 warps along N (32 cols each)
    const int g  = lane >> 2;       // 0..7
    const int tg = lane & 3;        // 0..3

    const int bm = blockIdx.y * BM;
    const int bn = blockIdx.x * BN;
    const bool g4 = (blockIdx.x >= 32) && (blockIdx.x < 40);   // cols [4096,5120)

    // cp.async mapping: each thread owns one 16B chunk per row-group
    const int lr = tid >> 3;            // 0..31
    const int lc = (tid & 7) * 4;       // 0,4,...,28

    float acc[4][4][4];
    #pragma unroll
    for (int mf = 0; mf < 4; mf++)
        #pragma unroll
        for (int nf = 0; nf < 4; nf++)
            #pragma unroll
            for (int r = 0; r < 4; r++) acc[mf][nf][r] = 0.0f;

    auto load_stage = [&](int i, int s) {
        const float* Ag = (i < 32) ? xin : hin;
        const float* Bg = (i < 32) ? W : U;
        const int k0 = (i & 31) * BK + lc;
        float* as = smem + s * TILE_FLOATS;
        float* bs = smem + (2 + s) * TILE_FLOATS;
        #pragma unroll
        for (int p = 0; p < 4; p++) {
            int row = lr + p * 32;
            cp_async16(&as[row * SS + lc], &Ag[(size_t)(bm + row) * KDIM + k0]);
            cp_async16(&bs[row * SS + lc], &Bg[(size_t)(bn + row) * KDIM + k0]);
        }
        asm volatile("cp.async.commit_group;\n" ::: "memory");
    };

    auto flush = [&](float* dst, int ncols, int coloff) {
        #pragma unroll
        for (int mf = 0; mf < 4; mf++) {
            #pragma unroll
            for (int nf = 0; nf < 4; nf++) {
                int row = bm + wm * 64 + mf * 16 + g;
                int col = coloff + wn * 32 + nf * 8 + 2 * tg;
                *(float2*)&dst[(size_t)row * ncols + col] =
                    make_float2(acc[mf][nf][0], acc[mf][nf][1]);
                *(float2*)&dst[(size_t)(row + 8) * ncols + col] =
                    make_float2(acc[mf][nf][2], acc[mf][nf][3]);
            }
        }
    };

    load_stage(0, 0);

    for (int i = 0; i < NK; i++) {
        const int s = i & 1;
        if (i + 1 < NK) {
            load_stage(i + 1, s ^ 1);
            asm volatile("cp.async.wait_group 1;\n" ::: "memory");
        } else {
            asm volatile("cp.async.wait_group 0;\n" ::: "memory");
        }
        __syncthreads();

        // float4 views of the current stage
        const float4* as4 = (const float4*)(smem + s * TILE_FLOATS);
        const float4* bs4 = (const float4*)(smem + (2 + s) * TILE_FLOATS);

        // k-quad remap: thread tg reads float4 at k-cols 4tg..4tg+3 within each
        // 16-col block; (x,y) feed k8-step0, (z,w) feed k8-step1. Same
        // (thread,slot)->column map for A and B => dot products unchanged.
        #pragma unroll
        for (int kb = 0; kb < 2; kb++) {          // two k16 blocks per BK=32
            float4 b4[4];
            #pragma unroll
            for (int nf = 0; nf < 4; nf++) {
                int c0 = wn * 32 + nf * 8 + g;
                b4[nf] = bs4[c0 * SQ + kb * 4 + tg];
            }
            #pragma unroll
            for (int mf = 0; mf < 4; mf++) {
                int rr = wm * 64 + mf * 16 + g;
                float4 lo = as4[rr * SQ + kb * 4 + tg];
                float4 hi = as4[(rr + 8) * SQ + kb * 4 + tg];
                uint32_t a0s0 = __float_as_uint(lo.x), a2s0 = __float_as_uint(lo.y);
                uint32_t a1s0 = __float_as_uint(hi.x), a3s0 = __float_as_uint(hi.y);
                uint32_t a0s1 = __float_as_uint(lo.z), a2s1 = __float_as_uint(lo.w);
                uint32_t a1s1 = __float_as_uint(hi.z), a3s1 = __float_as_uint(hi.w);
                #pragma unroll
                for (int nf = 0; nf < 4; nf++) {
                    asm volatile(
                        "mma.sync.aligned.m16n8k8.row.col.f32.tf32.tf32.f32 "
                        "{%0,%1,%2,%3}, {%4,%5,%6,%7}, {%8,%9}, {%0,%1,%2,%3};\n"
                        : "+f"(acc[mf][nf][0]), "+f"(acc[mf][nf][1]),
                          "+f"(acc[mf][nf][2]), "+f"(acc[mf][nf][3])
                        : "r"(a0s0), "r"(a1s0), "r"(a2s0), "r"(a3s0),
                          "r"(__float_as_uint(b4[nf].x)), "r"(__float_as_uint(b4[nf].y)));
                }
                #pragma unroll
                for (int nf = 0; nf < 4; nf++) {
                    asm volatile(
                        "mma.sync.aligned.m16n8k8.row.col.f32.tf32.tf32.f32 "
                        "{%0,%1,%2,%3}, {%4,%5,%6,%7}, {%8,%9}, {%0,%1,%2,%3};\n"
                        : "+f"(acc[mf][nf][0]), "+f"(acc[mf][nf][1]),
                          "+f"(acc[mf][nf][2]), "+f"(acc[mf][nf][3])
                        : "r"(a0s1), "r"(a1s1), "r"(a2s1), "r"(a3s1),
                          "r"(__float_as_uint(b4[nf].z)), "r"(__float_as_uint(b4[nf].w)));
                }
            }
        }
        __syncthreads();

        // Gate-4 midpoint flush: wx4 complete after first 32 k-tiles
        if (g4 && i == 31) {
            flush(Z, NDIM, bn);
            #pragma unroll
            for (int mf = 0; mf < 4; mf++)
                #pragma unroll
                for (int nf = 0; nf < 4; nf++)
                    #pragma unroll
                    for (int r = 0; r < 4; r++) acc[mf][nf][r] = 0.0f;
        }
    }

    if (g4) flush(U4, HDIM, bn - 4096);   // uh4
    else    flush(Z, NDIM, bn);           // wx + uh
}

__device__ __forceinline__ float sigmoidf_(float z) { return 1.0f / (1.0f + expf(-z)); }

__global__ __launch_bounds__(256)
void xlstm_epilogue_kernel(const float* __restrict__ c_prev,
                           const float* __restrict__ b_all,
                           float* __restrict__ out) {
    int q = blockIdx.x * blockDim.x + threadIdx.x;      // float4 index over [B*H/4)
    if (q >= BDIM * HDIM / 4) return;
    int b  = q >> 8;            // / 256
    int hq = q & 255;           // float4 col
    size_t base4 = (size_t)b * (NDIM / 4) + hq;

    const float4* Z4  = (const float4*)g_Z;
    const float4* U44 = (const float4*)g_U4;
    const float4* bb  = (const float4*)b_all;
    const float4* cp4 = (const float4*)c_prev;
    float4* out4 = (float4*)out;

    float4 z[6];
    #pragma unroll
    for (int k = 0; k < 6; k++) {
        float4 zz = Z4[base4 + (size_t)k * 256];
        float4 bv = bb[k * 256 + hq];
        z[k] = make_float4(zz.x + bv.x, zz.y + bv.y, zz.z + bv.z, zz.w + bv.w);
    }
    float4 u4 = U44[q];
    float4 cp = cp4[q];

    float4 hn, cn;
    {
        float i = sigmoidf_(z[0].x), f = sigmoidf_(z[1].x), o = sigmoidf_(z[2].x);
        float gg = tanhf(z[3].x), m = z[4].x * u4.x, a = sigmoidf_(z[5].x);
        cn.x = f * cp.x + i * gg + a * m;  hn.x = o * tanhf(cn.x);
    }
    {
        float i = sigmoidf_(z[0].y), f = sigmoidf_(z[1].y), o = sigmoidf_(z[2].y);
        float gg = tanhf(z[3].y), m = z[4].y * u4.y, a = sigmoidf_(z[5].y);
        cn.y = f * cp.y + i * gg + a * m;  hn.y = o * tanhf(cn.y);
    }
    {
        float i = sigmoidf_(z[0].z), f = sigmoidf_(z[1].z), o = sigmoidf_(z[2].z);
        float gg = tanhf(z[3].z), m = z[4].z * u4.z, a = sigmoidf_(z[5].z);
        cn.z = f * cp.z + i * gg + a * m;  hn.z = o * tanhf(cn.z);
    }
    {
        float i = sigmoidf_(z[0].w), f = sigmoidf_(z[1].w), o = sigmoidf_(z[2].w);
        float gg = tanhf(z[3].w), m = z[4].w * u4.w, a = sigmoidf_(z[5].w);
        cn.w = f * cp.w + i * gg + a * m;  hn.w = o * tanhf(cn.w);
    }

    out4[q] = hn;
    out4[(size_t)BDIM * HDIM / 4 + q] = cn;
}

extern "C" void kernel_launch(void* const* d_in, const int* in_sizes, int n_in,
                              void* d_out, int out_size) {
    const float* x      = (const float*)d_in[0];
    const float* h_prev = (const float*)d_in[1];
    const float* c_prev = (const float*)d_in[2];
    const float* W_all  = (const float*)d_in[3];
    const float* b_all  = (const float*)d_in[4];
    const float* U_all  = (const float*)d_in[5];
    float* out = (float*)d_out;

    float *pZ = nullptr, *pU4 = nullptr;
    cudaGetSymbolAddress((void**)&pZ, g_Z);
    cudaGetSymbolAddress((void**)&pU4, g_U4);

    const int smem_bytes = 4 * TILE_FLOATS * sizeof(float);   // 98304 B per CTA
    cudaFuncSetAttribute(xlstm_gemm_kernel,
                         cudaFuncAttributeMaxDynamicSharedMemorySize, smem_bytes);

    dim3 grid(NDIM / BN, BDIM / BM);   // 48 x 32
    xlstm_gemm_kernel<<<grid, 256, smem_bytes>>>(x, h_prev, W_all, U_all, pZ, pU4);

    int n4 = BDIM * HDIM / 4;
    xlstm_epilogue_kernel<<<(n4 + 255) / 256, 256>>>(c_prev, b_all, out);
}

// round 7
// speedup vs baseline: 1.5067x; 1.5067x over previous
#include <cuda_runtime.h>
#include <cuda_fp16.h>
#include <cstdint>
#include <cstddef>

// Problem dims
#define BDIM 4096
#define KDIM 1024
#define HDIM 1024
#define NDIM 6144           // 6 gates * H
#define KTOT 2048           // joint K (x|h concatenated)

// GEMM tiling: CTA 128x128, 8 warps of 64x32, 2 CTAs/SM, 2-stage cp.async
#define BM 128
#define BN 128
#define BK 32               // k-halfs per stage chunk = 64B rows (conflict-free LDS.128)
#define ROWB 64             // bytes per smem row
#define TILE_BYTES (128 * ROWB)          // 8192 B per matrix tile
#define STAGE_BYTES (2 * TILE_BYTES)     // A + B = 16384 B
#define NK 64               // 2048 / 32

// Scratch
__device__ __half g_Ah[(size_t)BDIM * KTOT];   // [x | h] fp16
__device__ __half g_Bh[(size_t)NDIM * KTOT];   // [W | U] fp16
__device__ float  g_Z[(size_t)BDIM * NDIM];    // wx+uh (gate-4 slot: wx4)
__device__ float  g_U4[(size_t)BDIM * HDIM];   // uh4

__device__ __forceinline__ void cp_async16(uint32_t smem_addr, const void* gmem_ptr) {
    asm volatile("cp.async.cg.shared.global [%0], [%1], 16;\n" :: "r"(smem_addr), "l"(gmem_ptr));
}

// ---------------- fp32 -> fp16 conversion (src is [nrows,1024] fp32) ----------------
__global__ __launch_bounds__(256)
void conv_half_kernel(const float* __restrict__ src, __half* __restrict__ dst,
                      int nrows, int col_off) {
    int q = blockIdx.x * blockDim.x + threadIdx.x;   // float4 index
    if (q >= nrows * 256) return;
    int row = q >> 8;
    int c   = (q & 255) * 4;
    float4 v = *(const float4*)&src[(size_t)row * 1024 + c];
    __half2 h0 = __floats2half2_rn(v.x, v.y);
    __half2 h1 = __floats2half2_rn(v.z, v.w);
    uint2 packed = make_uint2(*(uint32_t*)&h0, *(uint32_t*)&h1);
    *(uint2*)&dst[(size_t)row * KTOT + col_off + c] = packed;
}

// ---------------- fp16 GEMM: Z = Ah * Bh^T (K=2048), gate-4 midpoint split ----------------
__global__ __launch_bounds__(256, 2)
void xlstm_gemm_kernel(const __half* __restrict__ A, const __half* __restrict__ B,
                       float* __restrict__ Z, float* __restrict__ U4) {
    extern __shared__ char smem[];
    const uint32_t sbase = (uint32_t)__cvta_generic_to_shared(smem);

    const int tid  = threadIdx.x;
    const int warp = tid >> 5;
    const int lane = tid & 31;
    const int wm = warp & 1;        // 2 warps along M (64 rows each)
    const int wn = warp >> 1;       // 4 warps along N (32 cols each)
    const int g  = lane >> 2;       // 0..7
    const int tg = lane & 3;        // 0..3

    const int bm = blockIdx.y * BM;
    const int bn = blockIdx.x * BN;
    const bool g4 = (blockIdx.x >= 32) && (blockIdx.x < 40);   // cols [4096,5120)

    // cp.async mapping: thread covers 2 chunk-pairs per matrix per stage
    const int lr = tid >> 1;        // row 0..127
    const int lch = tid & 1;        // chunk 0/1 (also +2)

    float acc[4][4][4];
    #pragma unroll
    for (int mf = 0; mf < 4; mf++)
        #pragma unroll
        for (int nf = 0; nf < 4; nf++)
            #pragma unroll
            for (int r = 0; r < 4; r++) acc[mf][nf][r] = 0.0f;

    auto load_stage = [&](int i, int s) {
        const int k0 = i * BK;                       // half offset within KTOT
        const uint32_t as = sbase + s * STAGE_BYTES;
        const uint32_t bs = as + TILE_BYTES;
        const __half* ap = A + (size_t)(bm + lr) * KTOT + k0 + lch * 8;
        const __half* bp = B + (size_t)(bn + lr) * KTOT + k0 + lch * 8;
        cp_async16(as + lr * ROWB + lch * 16,      ap);
        cp_async16(as + lr * ROWB + lch * 16 + 32, ap + 16);
        cp_async16(bs + lr * ROWB + lch * 16,      bp);
        cp_async16(bs + lr * ROWB + lch * 16 + 32, bp + 16);
        asm volatile("cp.async.commit_group;\n" ::: "memory");
    };

    auto flush = [&](float* dst, int ncols, int coloff) {
        #pragma unroll
        for (int mf = 0; mf < 4; mf++) {
            #pragma unroll
            for (int nf = 0; nf < 4; nf++) {
                int row = bm + wm * 64 + mf * 16 + g;
                int col = coloff + wn * 32 + nf * 8 + 2 * tg;
                *(float2*)&dst[(size_t)row * ncols + col] =
                    make_float2(acc[mf][nf][0], acc[mf][nf][1]);
                *(float2*)&dst[(size_t)(row + 8) * ncols + col] =
                    make_float2(acc[mf][nf][2], acc[mf][nf][3]);
            }
        }
    };

    load_stage(0, 0);

    for (int i = 0; i < NK; i++) {
        const int s = i & 1;
        if (i + 1 < NK) {
            load_stage(i + 1, s ^ 1);
            asm volatile("cp.async.wait_group 1;\n" ::: "memory");
        } else {
            asm volatile("cp.async.wait_group 0;\n" ::: "memory");
        }
        __syncthreads();

        // uint4 views: 4 x 16B chunks per 64B row
        const uint4* as4 = (const uint4*)(smem + s * STAGE_BYTES);
        const uint4* bs4 = (const uint4*)(smem + s * STAGE_BYTES + TILE_BYTES);

        // k-remap: thread tg owns halves k in [8tg, 8tg+8). (x,y) feed k16-step0
        // slots (a0/a2, b0/b1), (z,w) feed step1. Same (thread,slot)->k map for
        // A and B => dot products unchanged (k-permutation invariance).
        uint4 bq[4];
        #pragma unroll
        for (int nf = 0; nf < 4; nf++) {
            int c0 = wn * 32 + nf * 8 + g;
            bq[nf] = bs4[c0 * 4 + tg];
        }
        #pragma unroll
        for (int mf = 0; mf < 4; mf++) {
            int rr = wm * 64 + mf * 16 + g;
            uint4 lo = as4[rr * 4 + tg];
            uint4 hi = as4[(rr + 8) * 4 + tg];
            #pragma unroll
            for (int nf = 0; nf < 4; nf++) {
                asm volatile(
                    "mma.sync.aligned.m16n8k16.row.col.f32.f16.f16.f32 "
                    "{%0,%1,%2,%3}, {%4,%5,%6,%7}, {%8,%9}, {%0,%1,%2,%3};\n"
                    : "+f"(acc[mf][nf][0]), "+f"(acc[mf][nf][1]),
                      "+f"(acc[mf][nf][2]), "+f"(acc[mf][nf][3])
                    : "r"(lo.x), "r"(hi.x), "r"(lo.y), "r"(hi.y),
                      "r"(bq[nf].x), "r"(bq[nf].y));
            }
            #pragma unroll
            for (int nf = 0; nf < 4; nf++) {
                asm volatile(
                    "mma.sync.aligned.m16n8k16.row.col.f32.f16.f16.f32 "
                    "{%0,%1,%2,%3}, {%4,%5,%6,%7}, {%8,%9}, {%0,%1,%2,%3};\n"
                    : "+f"(acc[mf][nf][0]), "+f"(acc[mf][nf][1]),
                      "+f"(acc[mf][nf][2]), "+f"(acc[mf][nf][3])
                    : "r"(lo.z), "r"(hi.z), "r"(lo.w), "r"(hi.w),
                      "r"(bq[nf].z), "r"(bq[nf].w));
            }
        }
        __syncthreads();

        // Gate-4 midpoint flush: wx4 complete after first 32 k-chunks (K=1024)
        if (g4 && i == 31) {
            flush(Z, NDIM, bn);
            #pragma unroll
            for (int mf = 0; mf < 4; mf++)
                #pragma unroll
                for (int nf = 0; nf < 4; nf++)
                    #pragma unroll
                    for (int r = 0; r < 4; r++) acc[mf][nf][r] = 0.0f;
        }
    }

    if (g4) flush(U4, HDIM, bn - 4096);   // uh4
    else    flush(Z, NDIM, bn);           // wx + uh
}

// ---------------- gate epilogue ----------------
__device__ __forceinline__ float sigmoidf_(float z) { return 1.0f / (1.0f + expf(-z)); }

__global__ __launch_bounds__(256)
void xlstm_epilogue_kernel(const float* __restrict__ c_prev,
                           const float* __restrict__ b_all,
                           float* __restrict__ out) {
    int q = blockIdx.x * blockDim.x + threadIdx.x;      // float4 index over [B*H/4)
    if (q >= BDIM * HDIM / 4) return;
    int b  = q >> 8;
    int hq = q & 255;
    size_t base4 = (size_t)b * (NDIM / 4) + hq;

    const float4* Z4  = (const float4*)g_Z;
    const float4* U44 = (const float4*)g_U4;
    const float4* bb  = (const float4*)b_all;
    const float4* cp4 = (const float4*)c_prev;
    float4* out4 = (float4*)out;

    float4 z[6];
    #pragma unroll
    for (int k = 0; k < 6; k++) {
        float4 zz = Z4[base4 + (size_t)k * 256];
        float4 bv = bb[k * 256 + hq];
        z[k] = make_float4(zz.x + bv.x, zz.y + bv.y, zz.z + bv.z, zz.w + bv.w);
    }
    float4 u4 = U44[q];
    float4 cp = cp4[q];

    float4 hn, cn;
    {
        float i = sigmoidf_(z[0].x), f = sigmoidf_(z[1].x), o = sigmoidf_(z[2].x);
        float gg = tanhf(z[3].x), m = z[4].x * u4.x, a = sigmoidf_(z[5].x);
        cn.x = f * cp.x + i * gg + a * m;  hn.x = o * tanhf(cn.x);
    }
    {
        float i = sigmoidf_(z[0].y), f = sigmoidf_(z[1].y), o = sigmoidf_(z[2].y);
        float gg = tanhf(z[3].y), m = z[4].y * u4.y, a = sigmoidf_(z[5].y);
        cn.y = f * cp.y + i * gg + a * m;  hn.y = o * tanhf(cn.y);
    }
    {
        float i = sigmoidf_(z[0].z), f = sigmoidf_(z[1].z), o = sigmoidf_(z[2].z);
        float gg = tanhf(z[3].z), m = z[4].z * u4.z, a = sigmoidf_(z[5].z);
        cn.z = f * cp.z + i * gg + a * m;  hn.z = o * tanhf(cn.z);
    }
    {
        float i = sigmoidf_(z[0].w), f = sigmoidf_(z[1].w), o = sigmoidf_(z[2].w);
        float gg = tanhf(z[3].w), m = z[4].w * u4.w, a = sigmoidf_(z[5].w);
        cn.w = f * cp.w + i * gg + a * m;  hn.w = o * tanhf(cn.w);
    }

    out4[q] = hn;
    out4[(size_t)BDIM * HDIM / 4 + q] = cn;
}

extern "C" void kernel_launch(void* const* d_in, const int* in_sizes, int n_in,
                              void* d_out, int out_size) {
    const float* x      = (const float*)d_in[0];
    const float* h_prev = (const float*)d_in[1];
    const float* c_prev = (const float*)d_in[2];
    const float* W_all  = (const float*)d_in[3];
    const float* b_all  = (const float*)d_in[4];
    const float* U_all  = (const float*)d_in[5];
    float* out = (float*)d_out;

    __half *pAh = nullptr, *pBh = nullptr;
    float *pZ = nullptr, *pU4 = nullptr;
    cudaGetSymbolAddress((void**)&pAh, g_Ah);
    cudaGetSymbolAddress((void**)&pBh, g_Bh);
    cudaGetSymbolAddress((void**)&pZ, g_Z);
    cudaGetSymbolAddress((void**)&pU4, g_U4);

    // Convert inputs to fp16: Ah = [x | h_prev], Bh = [W | U]
    conv_half_kernel<<<BDIM, 256>>>(x,      pAh, BDIM, 0);
    conv_half_kernel<<<BDIM, 256>>>(h_prev, pAh, BDIM, 1024);
    conv_half_kernel<<<NDIM, 256>>>(W_all,  pBh, NDIM, 0);
    conv_half_kernel<<<NDIM, 256>>>(U_all,  pBh, NDIM, 1024);

    const int smem_bytes = 2 * STAGE_BYTES;   // 32768 B per CTA
    cudaFuncSetAttribute(xlstm_gemm_kernel,
                         cudaFuncAttributeMaxDynamicSharedMemorySize, smem_bytes);

    dim3 grid(NDIM / BN, BDIM / BM);   // 48 x 32
    xlstm_gemm_kernel<<<grid, 256, smem_bytes>>>(pAh, pBh, pZ, pU4);

    int n4 = BDIM * HDIM / 4;
    xlstm_epilogue_kernel<<<(n4 + 255) / 256, 256>>>(c_prev, b_all, out);
}

// round 8
// speedup vs baseline: 1.5779x; 1.0472x over previous
#include <cuda_runtime.h>
#include <cuda_fp16.h>
#include <cstdint>
#include <cstddef>

// Problem dims
#define BDIM 4096
#define KDIM 1024
#define HDIM 1024
#define NDIM 6144           // 6 gates * H
#define KTOT 2048           // joint K (x|h concatenated)

// GEMM tiling: CTA 128x128, 8 warps of 64x32, 2 CTAs/SM, 4-stage cp.async, 1 sync/iter
#define BM 128
#define BN 128
#define BK 32               // halves per k-chunk = 64B rows (conflict-free LDS.128)
#define ROWB 64             // bytes per smem row
#define TILE_BYTES (128 * ROWB)          // 8192 B per matrix tile
#define STAGE_BYTES (2 * TILE_BYTES)     // A + B = 16384 B
#define NSTAGE 4
#define NK 64               // 2048 / 32

// Scratch
__device__ __half g_Ah[(size_t)BDIM * KTOT];   // [x | h] fp16
__device__ __half g_Bh[(size_t)NDIM * KTOT];   // [W | U] fp16
__device__ float  g_Z[(size_t)BDIM * NDIM];    // wx+uh (gate-4 slot: wx4)
__device__ float  g_U4[(size_t)BDIM * HDIM];   // uh4

__device__ __forceinline__ void cp_async16(uint32_t smem_addr, const void* gmem_ptr) {
    asm volatile("cp.async.cg.shared.global [%0], [%1], 16;\n" :: "r"(smem_addr), "l"(gmem_ptr));
}

// ---------------- merged fp32 -> fp16 conversion for all four tensors ----------------
// Segments (in float4 units): x[QX] -> Ah k0, h[QX] -> Ah k1024, W[QW] -> Bh k0, U[QW] -> Bh k1024
#define QX (BDIM * 256)
#define QW (NDIM * 256)
__global__ __launch_bounds__(256)
void conv_all_kernel(const float* __restrict__ x, const float* __restrict__ h,
                     const float* __restrict__ W, const float* __restrict__ Uu,
                     __half* __restrict__ Ah, __half* __restrict__ Bh) {
    int q = blockIdx.x * blockDim.x + threadIdx.x;
    const float* src;
    __half* dst;
    int local, koff;
    if (q < 2 * QX) {
        dst = Ah;
        if (q < QX) { src = x; local = q; koff = 0; }
        else        { src = h; local = q - QX; koff = 1024; }
    } else {
        int r = q - 2 * QX;
        if (r >= 2 * QW) return;
        dst = Bh;
        if (r < QW) { src = W;  local = r; koff = 0; }
        else        { src = Uu; local = r - QW; koff = 1024; }
    }
    int row = local >> 8;
    int c   = (local & 255) * 4;
    float4 v = *(const float4*)&src[(size_t)row * 1024 + c];
    __half2 h0 = __floats2half2_rn(v.x, v.y);
    __half2 h1 = __floats2half2_rn(v.z, v.w);
    uint2 packed = make_uint2(*(uint32_t*)&h0, *(uint32_t*)&h1);
    *(uint2*)&dst[(size_t)row * KTOT + koff + c] = packed;
}

// ---------------- fp16 GEMM: Z = Ah * Bh^T (K=2048), gate-4 midpoint split ----------------
__global__ __launch_bounds__(256, 2)
void xlstm_gemm_kernel(const __half* __restrict__ A, const __half* __restrict__ B,
                       float* __restrict__ Z, float* __restrict__ U4) {
    extern __shared__ char smem[];
    const uint32_t sbase = (uint32_t)__cvta_generic_to_shared(smem);

    const int tid  = threadIdx.x;
    const int warp = tid >> 5;
    const int lane = tid & 31;
    const int wm = warp & 1;        // 2 warps along M (64 rows each)
    const int wn = warp >> 1;       // 4 warps along N (32 cols each)
    const int g  = lane >> 2;       // 0..7
    const int tg = lane & 3;        // 0..3

    const int bm = blockIdx.y * BM;
    const int bn = blockIdx.x * BN;
    const bool g4 = (blockIdx.x >= 32) && (blockIdx.x < 40);   // cols [4096,5120)

    // cp.async mapping
    const int lr = tid >> 1;        // row 0..127
    const int lch = tid & 1;        // chunk 0/1 (also +2)

    float acc[4][4][4];
    #pragma unroll
    for (int mf = 0; mf < 4; mf++)
        #pragma unroll
        for (int nf = 0; nf < 4; nf++)
            #pragma unroll
            for (int r = 0; r < 4; r++) acc[mf][nf][r] = 0.0f;

    auto load_stage = [&](int i, int s) {
        const int k0 = i * BK;
        const uint32_t as = sbase + s * STAGE_BYTES;
        const uint32_t bs = as + TILE_BYTES;
        const __half* ap = A + (size_t)(bm + lr) * KTOT + k0 + lch * 8;
        const __half* bp = B + (size_t)(bn + lr) * KTOT + k0 + lch * 8;
        cp_async16(as + lr * ROWB + lch * 16,      ap);
        cp_async16(as + lr * ROWB + lch * 16 + 32, ap + 16);
        cp_async16(bs + lr * ROWB + lch * 16,      bp);
        cp_async16(bs + lr * ROWB + lch * 16 + 32, bp + 16);
        asm volatile("cp.async.commit_group;\n" ::: "memory");
    };

    auto flush = [&](float* dst, int ncols, int coloff) {
        #pragma unroll
        for (int mf = 0; mf < 4; mf++) {
            #pragma unroll
            for (int nf = 0; nf < 4; nf++) {
                int row = bm + wm * 64 + mf * 16 + g;
                int col = coloff + wn * 32 + nf * 8 + 2 * tg;
                *(float2*)&dst[(size_t)row * ncols + col] =
                    make_float2(acc[mf][nf][0], acc[mf][nf][1]);
                *(float2*)&dst[(size_t)(row + 8) * ncols + col] =
                    make_float2(acc[mf][nf][2], acc[mf][nf][3]);
            }
        }
    };

    // Prologue: fill 3 of 4 stages
    load_stage(0, 0);
    load_stage(1, 1);
    load_stage(2, 2);

    for (int i = 0; i < NK; i++) {
        // Ensure group i complete (groups i+1, i+2 may remain in flight)
        if (i < NK - 2)       asm volatile("cp.async.wait_group 2;\n" ::: "memory");
        else if (i == NK - 2) asm volatile("cp.async.wait_group 1;\n" ::: "memory");
        else                  asm volatile("cp.async.wait_group 0;\n" ::: "memory");
        __syncthreads();   // stage i ready AND stage (i-1)%4 fully consumed by all warps

        if (i + 3 < NK) load_stage(i + 3, (i + 3) & 3);

        const int s = i & 3;
        const uint4* as4 = (const uint4*)(smem + s * STAGE_BYTES);
        const uint4* bs4 = (const uint4*)(smem + s * STAGE_BYTES + TILE_BYTES);

        // k-remap: thread tg owns halves [8tg, 8tg+8); (x,y) feed k16-step0,
        // (z,w) feed step1. Same (thread,slot)->k map for A and B => dot
        // products unchanged (k-permutation invariance).
        uint4 bq[4];
        #pragma unroll
        for (int nf = 0; nf < 4; nf++) {
            int c0 = wn * 32 + nf * 8 + g;
            bq[nf] = bs4[c0 * 4 + tg];
        }
        #pragma unroll
        for (int mf = 0; mf < 4; mf++) {
            int rr = wm * 64 + mf * 16 + g;
            uint4 lo = as4[rr * 4 + tg];
            uint4 hi = as4[(rr + 8) * 4 + tg];
            #pragma unroll
            for (int nf = 0; nf < 4; nf++) {
                asm volatile(
                    "mma.sync.aligned.m16n8k16.row.col.f32.f16.f16.f32 "
                    "{%0,%1,%2,%3}, {%4,%5,%6,%7}, {%8,%9}, {%0,%1,%2,%3};\n"
                    : "+f"(acc[mf][nf][0]), "+f"(acc[mf][nf][1]),
                      "+f"(acc[mf][nf][2]), "+f"(acc[mf][nf][3])
                    : "r"(lo.x), "r"(hi.x), "r"(lo.y), "r"(hi.y),
                      "r"(bq[nf].x), "r"(bq[nf].y));
            }
            #pragma unroll
            for (int nf = 0; nf < 4; nf++) {
                asm volatile(
                    "mma.sync.aligned.m16n8k16.row.col.f32.f16.f16.f32 "
                    "{%0,%1,%2,%3}, {%4,%5,%6,%7}, {%8,%9}, {%0,%1,%2,%3};\n"
                    : "+f"(acc[mf][nf][0]), "+f"(acc[mf][nf][1]),
                      "+f"(acc[mf][nf][2]), "+f"(acc[mf][nf][3])
                    : "r"(lo.z), "r"(hi.z), "r"(lo.w), "r"(hi.w),
                      "r"(bq[nf].z), "r"(bq[nf].w));
            }
        }

        // Gate-4 midpoint flush: wx4 complete after first 32 k-chunks (K=1024)
        if (g4 && i == 31) {
            flush(Z, NDIM, bn);
            #pragma unroll
            for (int mf = 0; mf < 4; mf++)
                #pragma unroll
                for (int nf = 0; nf < 4; nf++)
                    #pragma unroll
                    for (int r = 0; r < 4; r++) acc[mf][nf][r] = 0.0f;
        }
    }

    if (g4) flush(U4, HDIM, bn - 4096);   // uh4
    else    flush(Z, NDIM, bn);           // wx + uh
}

// ---------------- gate epilogue ----------------
__device__ __forceinline__ float sigmoidf_(float z) { return 1.0f / (1.0f + expf(-z)); }

__global__ __launch_bounds__(256)
void xlstm_epilogue_kernel(const float* __restrict__ c_prev,
                           const float* __restrict__ b_all,
                           float* __restrict__ out) {
    int q = blockIdx.x * blockDim.x + threadIdx.x;      // float4 index over [B*H/4)
    if (q >= BDIM * HDIM / 4) return;
    int b  = q >> 8;
    int hq = q & 255;
    size_t base4 = (size_t)b * (NDIM / 4) + hq;

    const float4* Z4  = (const float4*)g_Z;
    const float4* U44 = (const float4*)g_U4;
    const float4* bb  = (const float4*)b_all;
    const float4* cp4 = (const float4*)c_prev;
    float4* out4 = (float4*)out;

    float4 z[6];
    #pragma unroll
    for (int k = 0; k < 6; k++) {
        float4 zz = Z4[base4 + (size_t)k * 256];
        float4 bv = bb[k * 256 + hq];
        z[k] = make_float4(zz.x + bv.x, zz.y + bv.y, zz.z + bv.z, zz.w + bv.w);
    }
    float4 u4 = U44[q];
    float4 cp = cp4[q];

    float4 hn, cn;
    {
        float i = sigmoidf_(z[0].x), f = sigmoidf_(z[1].x), o = sigmoidf_(z[2].x);
        float gg = tanhf(z[3].x), m = z[4].x * u4.x, a = sigmoidf_(z[5].x);
        cn.x = f * cp.x + i * gg + a * m;  hn.x = o * tanhf(cn.x);
    }
    {
        float i = sigmoidf_(z[0].y), f = sigmoidf_(z[1].y), o = sigmoidf_(z[2].y);
        float gg = tanhf(z[3].y), m = z[4].y * u4.y, a = sigmoidf_(z[5].y);
        cn.y = f * cp.y + i * gg + a * m;  hn.y = o * tanhf(cn.y);
    }
    {
        float i = sigmoidf_(z[0].z), f = sigmoidf_(z[1].z), o = sigmoidf_(z[2].z);
        float gg = tanhf(z[3].z), m = z[4].z * u4.z, a = sigmoidf_(z[5].z);
        cn.z = f * cp.z + i * gg + a * m;  hn.z = o * tanhf(cn.z);
    }
    {
        float i = sigmoidf_(z[0].w), f = sigmoidf_(z[1].w), o = sigmoidf_(z[2].w);
        float gg = tanhf(z[3].w), m = z[4].w * u4.w, a = sigmoidf_(z[5].w);
        cn.w = f * cp.w + i * gg + a * m;  hn.w = o * tanhf(cn.w);
    }

    out4[q] = hn;
    out4[(size_t)BDIM * HDIM / 4 + q] = cn;
}

extern "C" void kernel_launch(void* const* d_in, const int* in_sizes, int n_in,
                              void* d_out, int out_size) {
    const float* x      = (const float*)d_in[0];
    const float* h_prev = (const float*)d_in[1];
    const float* c_prev = (const float*)d_in[2];
    const float* W_all  = (const float*)d_in[3];
    const float* b_all  = (const float*)d_in[4];
    const float* U_all  = (const float*)d_in[5];
    float* out = (float*)d_out;

    __half *pAh = nullptr, *pBh = nullptr;
    float *pZ = nullptr, *pU4 = nullptr;
    cudaGetSymbolAddress((void**)&pAh, g_Ah);
    cudaGetSymbolAddress((void**)&pBh, g_Bh);
    cudaGetSymbolAddress((void**)&pZ, g_Z);
    cudaGetSymbolAddress((void**)&pU4, g_U4);

    // Single merged conversion kernel: Ah = [x | h_prev], Bh = [W | U]
    int total_q = 2 * QX + 2 * QW;
    conv_all_kernel<<<(total_q + 255) / 256, 256>>>(x, h_prev, W_all, U_all, pAh, pBh);

    const int smem_bytes = NSTAGE * STAGE_BYTES;   // 65536 B per CTA
    cudaFuncSetAttribute(xlstm_gemm_kernel,
                         cudaFuncAttributeMaxDynamicSharedMemorySize, smem_bytes);

    dim3 grid(NDIM / BN, BDIM / BM);   // 48 x 32
    xlstm_gemm_kernel<<<grid, 256, smem_bytes>>>(pAh, pBh, pZ, pU4);

    int n4 = BDIM * HDIM / 4;
    xlstm_epilogue_kernel<<<(n4 + 255) / 256, 256>>>(c_prev, b_all, out);
}

// round 10
// speedup vs baseline: 1.6342x; 1.0357x over previous
#include <cuda_runtime.h>
#include <cuda_fp16.h>
#include <cstdint>
#include <cstddef>

// Problem dims
#define BDIM 4096
#define HDIM 1024
#define NDIM 6144           // 6 gates * H (gate-interleaved: n' = h*6 + gate)
#define KTOT 2048           // joint K (x|h concatenated)

// GEMM tiling: CTA 128x96 (16 h-cols x 6 gates), 8 warps of 64x24, 2 CTAs/SM
#define BM 128
#define BN 96
#define BK 32               // halves per k-chunk = 64B rows (conflict-free LDS.128)
#define ROWB 64
#define A_TILE_BYTES (128 * ROWB)        // 8192
#define B_TILE_BYTES (96 * ROWB)         // 6144
#define STAGE_BYTES (A_TILE_BYTES + B_TILE_BYTES)   // 14336
#define NSTAGE 4
#define NK 64               // 2048 / 32
#define PIPE_OFF 512
#define ZST 132             // zs row stride (floats) — conflict-free STS
#define EPI_BYTES ((96 + 16) * ZST * 4)  // 59136
#define SMEM_TOTAL (PIPE_OFF + (EPI_BYTES > NSTAGE*STAGE_BYTES ? EPI_BYTES : NSTAGE*STAGE_BYTES))

// Scratch
__device__ __half g_Ah[(size_t)BDIM * KTOT];   // [x | h] fp16
__device__ __half g_Bh[(size_t)NDIM * KTOT];   // gate-interleaved [W | U] fp16

__device__ __forceinline__ void cp_async16(uint32_t smem_addr, const void* gmem_ptr) {
    asm volatile("cp.async.cg.shared.global [%0], [%1], 16;\n" :: "r"(smem_addr), "l"(gmem_ptr));
}

__device__ __forceinline__ float sigmoidf_(float z) { return 1.0f / (1.0f + expf(-z)); }

// ---------------- merged fp32 -> fp16 conversion ----------------
// x -> Ah[:,0:1024], h -> Ah[:,1024:], W -> Bh[h*6+g, 0:1024], U -> Bh[h*6+g, 1024:]
#define QX (BDIM * 256)
#define QW (NDIM * 256)
__global__ __launch_bounds__(256)
void conv_all_kernel(const float* __restrict__ x, const float* __restrict__ h,
                     const float* __restrict__ W, const float* __restrict__ Uu,
                     __half* __restrict__ Ah, __half* __restrict__ Bh) {
    int q = blockIdx.x * blockDim.x + threadIdx.x;
    const float* src;
    __half* dst;
    int local, koff;
    bool interleave;
    if (q < 2 * QX) {
        dst = Ah; interleave = false;
        if (q < QX) { src = x; local = q; koff = 0; }
        else        { src = h; local = q - QX; koff = 1024; }
    } else {
        int r = q - 2 * QX;
        if (r >= 2 * QW) return;
        dst = Bh; interleave = true;
        if (r < QW) { src = W;  local = r; koff = 0; }
        else        { src = Uu; local = r - QW; koff = 1024; }
    }
    int row = local >> 8;
    int c   = (local & 255) * 4;
    float4 v = *(const float4*)&src[(size_t)row * 1024 + c];
    __half2 h0 = __floats2half2_rn(v.x, v.y);
    __half2 h1 = __floats2half2_rn(v.z, v.w);
    uint2 packed = make_uint2(*(uint32_t*)&h0, *(uint32_t*)&h1);
    int drow = row;
    if (interleave) {                       // src row n = gate*1024 + hcol
        int gate = row >> 10, hcol = row & 1023;
        drow = hcol * 6 + gate;             // n' = h*6 + gate
    }
    *(uint2*)&dst[(size_t)drow * KTOT + koff + c] = packed;
}

// ------------- fused GEMM (Z = Ah*Bh^T, K=2048, gate-4 midpoint split) + gate epilogue -------------
__global__ __launch_bounds__(256, 2)
void xlstm_fused_kernel(const __half* __restrict__ A, const __half* __restrict__ B,
                        const float* __restrict__ c_prev, const float* __restrict__ b_all,
                        float* __restrict__ out) {
    extern __shared__ char smem[];
    const uint32_t sbase = (uint32_t)__cvta_generic_to_shared(smem);

    const int tid  = threadIdx.x;
    const int warp = tid >> 5;
    const int lane = tid & 31;
    const int wm = warp & 1;        // 2 warps along M (64 rows)
    const int wn = warp >> 1;       // 4 warps along N (24 cols)
    const int g  = lane >> 2;       // 0..7
    const int tg = lane & 3;        // 0..3

    const int bm = blockIdx.y * BM;
    const int bnp = blockIdx.x * BN;     // interleaved-col offset
    const int h0 = blockIdx.x * 16;      // h block base

    const int lr = tid >> 1;        // 0..127
    const int lch = tid & 1;

    float acc[4][3][4];
    float wx4[4][2];
    #pragma unroll
    for (int mf = 0; mf < 4; mf++) {
        wx4[mf][0] = wx4[mf][1] = 0.0f;
        #pragma unroll
        for (int nf = 0; nf < 3; nf++)
            #pragma unroll
            for (int r = 0; r < 4; r++) acc[mf][nf][r] = 0.0f;
    }

    auto load_stage = [&](int i, int s) {
        const int k0 = i * BK;
        const uint32_t as = sbase + PIPE_OFF + s * STAGE_BYTES;
        const uint32_t bs = as + A_TILE_BYTES;
        const __half* ap = A + (size_t)(bm + lr) * KTOT + k0 + lch * 8;
        cp_async16(as + lr * ROWB + lch * 16,      ap);
        cp_async16(as + lr * ROWB + lch * 16 + 32, ap + 16);
        {   // B chunk tid (rows 0..63)
            int row = tid >> 2, ch = tid & 3;
            cp_async16(bs + row * ROWB + ch * 16,
                       B + (size_t)(bnp + row) * KTOT + k0 + ch * 8);
        }
        if (tid < 128) {   // B chunk tid+256 (rows 64..95)
            int cb = tid + 256;
            int row = cb >> 2, ch = cb & 3;
            cp_async16(bs + row * ROWB + ch * 16,
                       B + (size_t)(bnp + row) * KTOT + k0 + ch * 8);
        }
        asm volatile("cp.async.commit_group;\n" ::: "memory");
    };

    load_stage(0, 0);
    load_stage(1, 1);
    load_stage(2, 2);

    const int nf4 = (2 - tg + 3) % 3;    // the nf whose col-pair is (gate4, gate5)

    for (int i = 0; i < NK; i++) {
        if (i < NK - 2)       asm volatile("cp.async.wait_group 2;\n" ::: "memory");
        else if (i == NK - 2) asm volatile("cp.async.wait_group 1;\n" ::: "memory");
        else                  asm volatile("cp.async.wait_group 0;\n" ::: "memory");
        __syncthreads();

        if (i + 3 < NK) load_stage(i + 3, (i + 3) & 3);

        const int s = i & 3;
        const uint4* as4 = (const uint4*)(smem + PIPE_OFF + s * STAGE_BYTES);
        const uint4* bs4 = (const uint4*)(smem + PIPE_OFF + s * STAGE_BYTES + A_TILE_BYTES);

        // k-remap: thread tg owns halves [8tg,8tg+8); (x,y) -> k16-step0 slots,
        // (z,w) -> step1. Same map for A and B => dot products unchanged.
        uint4 bq[3];
        #pragma unroll
        for (int nf = 0; nf < 3; nf++) {
            int c0 = wn * 24 + nf * 8 + g;
            bq[nf] = bs4[c0 * 4 + tg];
        }
        #pragma unroll
        for (int mf = 0; mf < 4; mf++) {
            int rr = wm * 64 + mf * 16 + g;
            uint4 lo = as4[rr * 4 + tg];
            uint4 hi = as4[(rr + 8) * 4 + tg];
            #pragma unroll
            for (int nf = 0; nf < 3; nf++) {
                asm volatile(
                    "mma.sync.aligned.m16n8k16.row.col.f32.f16.f16.f32 "
                    "{%0,%1,%2,%3}, {%4,%5,%6,%7}, {%8,%9}, {%0,%1,%2,%3};\n"
                    : "+f"(acc[mf][nf][0]), "+f"(acc[mf][nf][1]),
                      "+f"(acc[mf][nf][2]), "+f"(acc[mf][nf][3])
                    : "r"(lo.x), "r"(hi.x), "r"(lo.y), "r"(hi.y),
                      "r"(bq[nf].x), "r"(bq[nf].y));
            }
            #pragma unroll
            for (int nf = 0; nf < 3; nf++) {
                asm volatile(
                    "mma.sync.aligned.m16n8k16.row.col.f32.f16.f16.f32 "
                    "{%0,%1,%2,%3}, {%4,%5,%6,%7}, {%8,%9}, {%0,%1,%2,%3};\n"
                    : "+f"(acc[mf][nf][0]), "+f"(acc[mf][nf][1]),
                      "+f"(acc[mf][nf][2]), "+f"(acc[mf][nf][3])
                    : "r"(lo.z), "r"(hi.z), "r"(lo.w), "r"(hi.w),
                      "r"(bq[nf].z), "r"(bq[nf].w));
            }
        }

        // Midpoint (end of x*W half): save gate-4 cols (wx4) and reset them;
        // all other gates keep joint accumulation of wx+uh.
        if (i == 31) {
            #pragma unroll
            for (int nf = 0; nf < 3; nf++) {
                if (nf == nf4) {
                    #pragma unroll
                    for (int mf = 0; mf < 4; mf++) {
                        wx4[mf][0] = acc[mf][nf][0];
                        wx4[mf][1] = acc[mf][nf][2];
                        acc[mf][nf][0] = 0.0f;
                        acc[mf][nf][2] = 0.0f;
                    }
                }
            }
        }
    }

    // -------- in-CTA gate epilogue --------
    __syncthreads();                       // all LDS of final stage consumed
    float* zs   = (float*)(smem + PIPE_OFF);        // [96][ZST]
    float* wx4s = zs + 96 * ZST;                    // [16][ZST]

    // h-local index of this thread's gate-4 column:
    // c = wn*24 + nf4*8 + 2tg  ->  h_local = wn*4 + (nf4*8 + 2tg)/6
    const int hl4 = wn * 4 + (nf4 * 8 + 2 * tg) / 6;

    #pragma unroll
    for (int mf = 0; mf < 4; mf++) {
        int row = wm * 64 + mf * 16 + g;
        #pragma unroll
        for (int nf = 0; nf < 3; nf++) {
            int col = wn * 24 + nf * 8 + 2 * tg;
            zs[col * ZST + row]           = acc[mf][nf][0];
            zs[(col + 1) * ZST + row]     = acc[mf][nf][1];
            zs[col * ZST + row + 8]       = acc[mf][nf][2];
            zs[(col + 1) * ZST + row + 8] = acc[mf][nf][3];
        }
        wx4s[hl4 * ZST + row]     = wx4[mf][0];
        wx4s[hl4 * ZST + row + 8] = wx4[mf][1];
    }
    __syncthreads();

    const int hl   = tid & 15;
    const int bgrp = tid >> 4;             // 0..15, 8 rows each
    const int hg   = h0 + hl;
    const float b0 = b_all[hg];
    const float b1 = b_all[1024 + hg];
    const float b2 = b_all[2048 + hg];
    const float b3 = b_all[3072 + hg];
    const float b4 = b_all[4096 + hg];
    const float b5 = b_all[5120 + hg];

    #pragma unroll
    for (int r = 0; r < 8; r++) {
        int b = bgrp * 8 + r;
        int bg = bm + b;
        float z0 = zs[(hl * 6 + 0) * ZST + b] + b0;
        float z1 = zs[(hl * 6 + 1) * ZST + b] + b1;
        float z2 = zs[(hl * 6 + 2) * ZST + b] + b2;
        float z3 = zs[(hl * 6 + 3) * ZST + b] + b3;
        float u4 = zs[(hl * 6 + 4) * ZST + b];          // uh4 (second half only)
        float z5 = zs[(hl * 6 + 5) * ZST + b] + b5;
        float w4 = wx4s[hl * ZST + b] + b4;             // wx4 + bias

        float ig = sigmoidf_(z0);
        float fg = sigmoidf_(z1);
        float og = sigmoidf_(z2);
        float gg = tanhf(z3);
        float m  = w4 * u4;
        float ag = sigmoidf_(z5);

        float cp = c_prev[(size_t)bg * HDIM + hg];
        float cn = fg * cp + ig * gg + ag * m;
        float hn = og * tanhf(cn);

        out[(size_t)bg * HDIM + hg] = hn;
        out[(size_t)BDIM * HDIM + (size_t)bg * HDIM + hg] = cn;
    }
}

extern "C" void kernel_launch(void* const* d_in, const int* in_sizes, int n_in,
                              void* d_out, int out_size) {
    const float* x      = (const float*)d_in[0];
    const float* h_prev = (const float*)d_in[1];
    const float* c_prev = (const float*)d_in[2];
    const float* W_all  = (const float*)d_in[3];
    const float* b_all  = (const float*)d_in[4];
    const float* U_all  = (const float*)d_in[5];
    float* out = (float*)d_out;

    __half *pAh = nullptr, *pBh = nullptr;
    cudaGetSymbolAddress((void**)&pAh, g_Ah);
    cudaGetSymbolAddress((void**)&pBh, g_Bh);

    int total_q = 2 * QX + 2 * QW;
    conv_all_kernel<<<(total_q + 255) / 256, 256>>>(x, h_prev, W_all, U_all, pAh, pBh);

    cudaFuncSetAttribute(xlstm_fused_kernel,
                         cudaFuncAttributeMaxDynamicSharedMemorySize, SMEM_TOTAL);

    dim3 grid(HDIM / 16, BDIM / BM);   // 64 x 32
    xlstm_fused_kernel<<<grid, 256, SMEM_TOTAL>>>(pAh, pBh, c_prev, b_all, out);
}